// round 15
// baseline (speedup 1.0000x reference)
#include <cuda_runtime.h>
#include <math.h>

// Problem constants (fixed by the reference)
#define BB 4096
#define TT 200
#define CC 38
#define SS 30
#define FULLMASK 0xffffffffu
#define CTC_BLOCKS 512            // 4096 warps = 1 per sample
#define D_BLOCKS   1024           // 8192 warps = 2 per sample (100 rows each)
#define KL_BLOCKS  3840           // 30720 warps x 4 rows each = BB*SS = 122880 rows
#define TOTAL_BLOCKS (CTC_BLOCKS + D_BLOCKS + KL_BLOCKS)
#define LN2 0.6931471805599453

// Scratch (no cudaMalloc allowed)
__device__ double   g_ctcraw[BB];     // log(unnormalized alpha_end); -1e30 = impossible
__device__ double   g_d2[BB * 2];     // per-(b,halfT) sum of log2(D_t)
__device__ float    g_klb[KL_BLOCKS]; // per-block KL partial sums
__device__ unsigned g_done;           // last-block-done counter (reset in-kernel)

// ---------------------------------------------------------------------------
// fp64 fallback (proven numerics): rerun one sample's full CTC forward with
// explicit emissions exp(x-2). Returns raw log(alpha_end). Rare.
// ---------------------------------------------------------------------------
__device__ __noinline__ double ctc_fp64(
    const float* __restrict__ xp, const int* __restrict__ target,
    int b, int il, int tl)
{
    const int lane = threadIdx.x & 31;
    int tg  = (lane < SS) ? target[b * SS + lane] : 1;
    int tgp = __shfl_up_sync(FULLMASK, tg, 1);
    const bool skip = (lane == 0 || tg != tgp);

    double ae = (lane == 0) ? 1.0 : 0.0;
    double ao = 0.0;
    for (int t = 0; t < il; ++t) {
        const float* r = xp + (size_t)t * CC;
        float pbe = __expf(r[0] - 2.0f);
        float ple = __expf(r[tg] - 2.0f);
        double op = __shfl_up_sync(FULLMASK, ao, 1);
        if (lane == 0) op = 0.0;
        double ne = (ae + op) * (double)pbe;
        double no = (ao + ae + (skip ? op : 0.0)) * (double)ple;
        ae = (lane <= 30) ? ne : 0.0;
        ao = (lane < 30) ? no : 0.0;
    }
    double aev = __shfl_sync(FULLMASK, ae, tl);
    double aov = __shfl_sync(FULLMASK, ao, tl - 1);
    double s = aev + aov;
    return (s > 0.0) ? log(s) : -1e30;
}

// ---------------------------------------------------------------------------
// CTC recursion (beta form), one warp per sample. (R9/R13-proven, untouched.)
// ---------------------------------------------------------------------------
__device__ __forceinline__ void ctc_body(
    const float* __restrict__ x, const int* __restrict__ target,
    const int* __restrict__ ilen, const int* __restrict__ tlen, int b)
{
    const int lane = threadIdx.x & 31;
    const bool valid = (lane >= 1 && lane <= SS);

    int tg  = valid ? target[b * SS + (lane - 1)] : 1;
    int tgp = __shfl_up_sync(FULLMASK, tg, 1);
    const float skipf = (lane == 1 || tg != tgp) ? 1.0f : 0.0f;

    const int il = ilen[b];
    const int tl = tlen[b];
    const float* xp = x + (size_t)b * TT * CC;

    float ae = (lane == 1) ? 1.0f : 0.0f;   // beta[2(lane-1)]
    float ao = 0.0f;                        // beta[2(lane-1)+1]
    int   Esum = 0;                         // true beta = stored * 2^Esum
    float bs = 0.0f, bsc = 0.0f;            // Kahan sum of (x0_t - 2)

    auto step = [&](float d) {
        float e  = __expf(d);                        // p_l / p_b
        float op = __shfl_up_sync(FULLMASK, ao, 1);  // lane0: own ao = 0
        float v  = ae + ao;                          // off-chain
        ae = ae + op;
        ao = fmaf(skipf, op, v) * e;
    };
    auto apply = [&](float m) {   // warp-uniform 2^k rescale, center 2^30
        unsigned mb = __float_as_uint(m);
        if (mb >= 0x00800000u && mb < 0x7f800000u) {
            int e = (int)(mb >> 23) - 127;
            int k = 30 - e;
            k = (k > 127) ? 127 : (k < -126 ? -126 : k);
            float sc = __uint_as_float((unsigned)(127 + k) << 23);
            ae *= sc; ao *= sc;
            Esum -= k;
        }
    };
    auto kadd = [&](float y0) {   // Kahan add into (bs, bsc)
        float y = y0 - bsc;
        float t = bs + y;
        bsc = (t - bs) - y;
        bs = t;
    };

    if (il == TT) {
        float cd[8]; float cbs;
        {
            float g = 0.0f;
#pragma unroll
            for (int i = 0; i < 8; ++i) {
                float b0 = xp[i * CC];
                float tv = xp[i * CC + tg];
                cd[i] = valid ? (tv - b0) : -1e30f;   // -1e30 kills ghost lanes
                g += b0;
            }
            cbs = g - 16.0f;
        }
        for (int g = 0; g < TT / 8; ++g) {
            float nd[8]; float nbs = 0.0f;
            if (g + 1 < TT / 8) {
                const float* np = xp + (size_t)(g + 1) * 8 * CC;
                float gsum = 0.0f;
#pragma unroll
                for (int i = 0; i < 8; ++i) {
                    float b0 = np[i * CC];
                    float tv = np[i * CC + tg];
                    nd[i] = valid ? (tv - b0) : -1e30f;
                    gsum += b0;
                }
                nbs = gsum - 16.0f;
            } else {
#pragma unroll
                for (int i = 0; i < 8; ++i) nd[i] = -1e30f;
            }
            kadd(cbs);
            step(cd[0]);
            step(cd[1]);
            step(cd[2]);
            step(cd[3]);
            // deferred max: measured here, butterfly overlaps steps 4..7
            float m = fmaxf(ae, ao);
            step(cd[4]);
            m = fmaxf(m, __shfl_xor_sync(FULLMASK, m, 16));
            step(cd[5]);
            m = fmaxf(m, __shfl_xor_sync(FULLMASK, m, 8));
            step(cd[6]);
            m = fmaxf(m, __shfl_xor_sync(FULLMASK, m, 4));
            step(cd[7]);
            m = fmaxf(m, __shfl_xor_sync(FULLMASK, m, 2));
            m = fmaxf(m, __shfl_xor_sync(FULLMASK, m, 1));
            apply(m);
#pragma unroll
            for (int i = 0; i < 8; ++i) cd[i] = nd[i];
            cbs = nbs;
        }
    } else {
        for (int t = 0; t < il; ++t) {
            const float* r = xp + (size_t)t * CC;
            float b0 = r[0];
            float d = valid ? (r[tg] - b0) : -1e30f;
            kadd(b0 - 2.0f);
            step(d);
            if ((t & 7) == 7) {
                float m = fmaxf(ae, ao);
#pragma unroll
                for (int o = 16; o > 0; o >>= 1)
                    m = fmaxf(m, __shfl_xor_sync(FULLMASK, m, o));
                apply(m);
            }
        }
    }

    // state 2*tl (even) -> lane tl+1 ; state 2*tl-1 (odd) -> lane tl
    float aev = __shfl_sync(FULLMASK, ae, tl + 1);
    float aov = __shfl_sync(FULLMASK, ao, tl);
    double ssum = (double)aev + (double)aov;

    if (ssum >= 8.673617379884035e-19 /* 2^-60 */ && ssum < 6.0e38) {
        if (lane == 0)
            g_ctcraw[b] = log(ssum) + (double)Esum * LN2 + (double)bs;
    } else {
        double raw = ctc_fp64(xp, target, b, il, tl);
        if (lane == 0) g_ctcraw[b] = raw;
    }
}

// ---------------------------------------------------------------------------
// Softmax-denominator pass, width-16, depth-1 software pipeline (R13-proven):
// warp w -> sample b=w/2, 100 rows. Half-warps process two consecutive rows;
// next pair's loads issued while current pair reduces. Running product P
// with exponent stripping.
// ---------------------------------------------------------------------------
__device__ __forceinline__ void d_body(
    const float* __restrict__ x, const int* __restrict__ ilen, int w)
{
    const int lane = threadIdx.x & 31;
    const int sub  = lane & 15;
    const int half = lane >> 4;
    const int b  = w >> 1;
    const int t0 = (w & 1) * 100;
    const int il = ilen[b];
    const int tend = (il < t0 + 100) ? il : (t0 + 100);

    const float* xp = x + (size_t)b * TT * CC;
    float P = 1.0f;
    int   Le = 0;
    int   it = 0;

    int t = t0;
    float2 cv = make_float2(-1e30f, -1e30f);
    float  ct = -1e30f;
    if (t + 2 <= tend) {
        const float* rb = xp + (size_t)(t + half) * CC;
        cv = ((const float2*)rb)[sub];
        ct = (sub >= 10) ? rb[22 + sub] : -1e30f;
    }
    for (; t + 2 <= tend; ++it) {
        const int tn = t + 2;
        float2 nv = make_float2(-1e30f, -1e30f);
        float  nt = -1e30f;
        if (tn + 2 <= tend) {
            const float* rb = xp + (size_t)(tn + half) * CC;
            nv = ((const float2*)rb)[sub];
            nt = (sub >= 10) ? rb[22 + sub] : -1e30f;
        }
        float e = __expf(cv.x - 2.0f) + __expf(cv.y - 2.0f) + __expf(ct - 2.0f);
#pragma unroll
        for (int o = 8; o > 0; o >>= 1)                      // within-half butterfly
            e += __shfl_xor_sync(FULLMASK, e, o);
        P *= e;                                              // own half's row sum
        if ((it & 7) == 7) {                                 // strip exponent
            unsigned pb = __float_as_uint(P);
            Le += (int)(pb >> 23) - 127;
            P = __uint_as_float((pb & 0x807fffffu) | 0x3f800000u);
        }
        cv = nv; ct = nt; t = tn;
    }
    if (t < tend) {                                          // odd remainder: half 0 only
        if (half == 0) {
            const float* rb = xp + (size_t)t * CC;
            float2 v = ((const float2*)rb)[sub];
            float tail = (sub >= 10) ? rb[22 + sub] : -1e30f;
            float e = __expf(v.x - 2.0f) + __expf(v.y - 2.0f) + __expf(tail - 2.0f);
#pragma unroll
            for (int o = 8; o > 0; o >>= 1)
                e += __shfl_xor_sync(0x0000ffffu, e, o);
            P *= e;
        }
    }
    double l2 = (double)Le + log2((double)P);
    double other = __shfl_xor_sync(FULLMASK, l2, 16);
    if (lane == 0) g_d2[w] = l2 + other;                     // sum of both halves
}

// ---------------------------------------------------------------------------
// KL smoothing (inline, R13-proven): one warp per (b,s) row; lane l<19 holds
// classes 2l, 2l+1. W derived from S (W = S + 38e-10).
// ---------------------------------------------------------------------------
__device__ __forceinline__ float kl_val(
    const float* __restrict__ x, const int* __restrict__ target,
    const int* __restrict__ tlen, const int* __restrict__ pos,
    const float* __restrict__ ms, int idx)
{
    const int lane = threadIdx.x & 31;
    const int b = idx / SS;
    const int s = idx - b * SS;

    const int tl = tlen[b];
    if (s >= tl) return 0.0f;

    const int p  = pos[b * SS + s];
    const int tg = target[b * SS + s];
    const int f  = (s == 0) ? (CC - 1) : target[b * SS + s - 1];

    const float* row = x + ((size_t)b * TT + p) * CC;
    const float* msr = ms + ((size_t)(f - 1) * 37 + (tg - 1)) * 37;

    float Ev = 0.0f, Tm = 0.0f, Sv = 0.0f;
    if (lane < 19) {
        float2 xv = ((const float2*)row)[lane];
        float se = (lane == 0) ? 0.0f : msr[2 * lane - 1];   // SLS class 2l
        float so = msr[2 * lane];                            // SLS class 2l+1
        float te = se + 1e-10f;
        float to = so + 1e-10f;
        Ev = __expf(xv.x) + __expf(xv.y);
        Tm = te * (__logf(te) - xv.x) + to * (__logf(to) - xv.y);
        Sv = se + so;
    }
#pragma unroll
    for (int o = 16; o > 0; o >>= 1) {
        Ev += __shfl_xor_sync(FULLMASK, Ev, o);
        Tm += __shfl_xor_sync(FULLMASK, Tm, o);
        Sv += __shfl_xor_sync(FULLMASK, Sv, o);
    }
    float lse = __logf(Ev);
    float W = Sv + 38e-10f;                                  // sum of t_c
    float klrow = (Tm + lse * W) * (1.0f / (float)CC);
    float L = (float)tl;
    float smooth = -expm1f(-0.05129329438755058f / L);       // 1 - 0.95^(1/L)
    return (smooth / L) * Sv * klrow;
}

// ---------------------------------------------------------------------------
// Single fused kernel (R13 structure + last-block final reduction).
// CTC blocks first (longest, LPT order), then D, then KL (4 sequential
// kl_val rows per warp, exactly as R13). The LAST block to arrive performs
// the deterministic final reduction (same fixed-order sum regardless of
// which block runs it) and resets the counter for graph replay.
// ---------------------------------------------------------------------------
__global__ void __launch_bounds__(256) mega_kernel(
    const float* __restrict__ x, const int* __restrict__ target,
    const int* __restrict__ ilen, const int* __restrict__ tlen,
    const int* __restrict__ pos, const float* __restrict__ ms,
    float* __restrict__ out)
{
    __shared__ float  ksum[8];
    __shared__ int    lastflag;
    __shared__ double sm[256];

    const int warp = threadIdx.x >> 5;
    if (blockIdx.x < CTC_BLOCKS) {
        ctc_body(x, target, ilen, tlen, blockIdx.x * 8 + warp);
    } else if (blockIdx.x < CTC_BLOCKS + D_BLOCKS) {
        d_body(x, ilen, (blockIdx.x - CTC_BLOCKS) * 8 + warp);
    } else {
        const int kb = blockIdx.x - CTC_BLOCKS - D_BLOCKS;
        const int base = (kb * 8 + warp) * 4;
        float v = 0.0f;
#pragma unroll
        for (int r = 0; r < 4; ++r)
            v += kl_val(x, target, tlen, pos, ms, base + r);
        if ((threadIdx.x & 31) == 0) ksum[warp] = v;
        __syncthreads();
        if (threadIdx.x == 0) {
            float t = 0.0f;
#pragma unroll
            for (int i = 0; i < 8; ++i) t += ksum[i];
            g_klb[kb] = t;
        }
    }

    // ---- arrival: publish this block's results, count down ----
    __threadfence();
    __syncthreads();
    if (threadIdx.x == 0) {
        unsigned v = atomicAdd(&g_done, 1u);
        lastflag = (v == (unsigned)(TOTAL_BLOCKS - 1));
    }
    __syncthreads();
    if (!lastflag) return;

    // ---- last block: deterministic final reduction (L2-hot data) ----
    __threadfence();   // acquire all published writes
    const int tid = threadIdx.x;
    double acc = 0.0;
#pragma unroll 5
    for (int i = tid; i < KL_BLOCKS; i += 256)
        acc += (double)g_klb[i];
#pragma unroll 4
    for (int b2 = tid; b2 < BB; b2 += 256) {
        double lnD = (g_d2[2 * b2] + g_d2[2 * b2 + 1]) * LN2;
        double nll = -(g_ctcraw[b2] - lnD);
        if (nll > 1e8) nll = 0.0;                            // zero_infinity
        acc += (nll / (double)tlen[b2]) * (1.0 / (double)BB);
    }
    sm[tid] = acc;
    __syncthreads();
    for (int st = 128; st > 0; st >>= 1) {
        if (tid < st) sm[tid] += sm[tid + st];
        __syncthreads();
    }
    if (tid == 0) {
        out[0] = (float)sm[0];
        g_done = 0;                       // reset for next graph replay
    }
}

// ---------------------------------------------------------------------------
extern "C" void kernel_launch(void* const* d_in, const int* in_sizes, int n_in,
                              void* d_out, int out_size)
{
    const float* x      = (const float*)d_in[0];   // [B,T,C] f32
    const int*   target = (const int*)d_in[1];     // [B,S]   i32
    const int*   ilen   = (const int*)d_in[2];     // [B]     i32
    const int*   tlen   = (const int*)d_in[3];     // [B]     i32
    const int*   pos    = (const int*)d_in[4];     // [B,S]   i32
    const float* ms     = (const float*)d_in[5];   // [37,37,37] f32

    mega_kernel<<<TOTAL_BLOCKS, 256>>>(x, target, ilen, tlen, pos, ms,
                                       (float*)d_out);
}

// round 16
// speedup vs baseline: 1.2591x; 1.2591x over previous
#include <cuda_runtime.h>
#include <math.h>

// Problem constants (fixed by the reference)
#define BB 4096
#define TT 200
#define CC 38
#define SS 30
#define FULLMASK 0xffffffffu
#define CTC_BLOCKS 512            // 4096 warps = 1 per sample
#define D_BLOCKS   1024           // 8192 warps = 2 per sample (100 rows each)
#define KL_BLOCKS  3840           // 30720 warps x 4 rows each = BB*SS = 122880 rows
#define TOTAL_BLOCKS (CTC_BLOCKS + D_BLOCKS + KL_BLOCKS)
#define LN2 0.6931471805599453

// Scratch (no cudaMalloc allowed)
__device__ double g_ctcraw[BB];     // log(unnormalized alpha_end); -1e30 = impossible
__device__ double g_d2[BB * 2];     // per-(b,halfT) sum of log2(D_t)
__device__ float  g_klb[KL_BLOCKS]; // per-block KL partial sums

// ---------------------------------------------------------------------------
// fp64 fallback (proven numerics): rerun one sample's full CTC forward with
// explicit emissions exp(x-2). Returns raw log(alpha_end). Rare.
// ---------------------------------------------------------------------------
__device__ __noinline__ double ctc_fp64(
    const float* __restrict__ xp, const int* __restrict__ target,
    int b, int il, int tl)
{
    const int lane = threadIdx.x & 31;
    int tg  = (lane < SS) ? target[b * SS + lane] : 1;
    int tgp = __shfl_up_sync(FULLMASK, tg, 1);
    const bool skip = (lane == 0 || tg != tgp);

    double ae = (lane == 0) ? 1.0 : 0.0;
    double ao = 0.0;
    for (int t = 0; t < il; ++t) {
        const float* r = xp + (size_t)t * CC;
        float pbe = __expf(r[0] - 2.0f);
        float ple = __expf(r[tg] - 2.0f);
        double op = __shfl_up_sync(FULLMASK, ao, 1);
        if (lane == 0) op = 0.0;
        double ne = (ae + op) * (double)pbe;
        double no = (ao + ae + (skip ? op : 0.0)) * (double)ple;
        ae = (lane <= 30) ? ne : 0.0;
        ao = (lane < 30) ? no : 0.0;
    }
    double aev = __shfl_sync(FULLMASK, ae, tl);
    double aov = __shfl_sync(FULLMASK, ao, tl - 1);
    double s = aev + aov;
    return (s > 0.0) ? log(s) : -1e30;
}

// ---------------------------------------------------------------------------
// CTC recursion (beta form), one warp per sample. (R9/R13-proven, untouched.)
// ---------------------------------------------------------------------------
__device__ __forceinline__ void ctc_body(
    const float* __restrict__ x, const int* __restrict__ target,
    const int* __restrict__ ilen, const int* __restrict__ tlen, int b)
{
    const int lane = threadIdx.x & 31;
    const bool valid = (lane >= 1 && lane <= SS);

    int tg  = valid ? target[b * SS + (lane - 1)] : 1;
    int tgp = __shfl_up_sync(FULLMASK, tg, 1);
    const float skipf = (lane == 1 || tg != tgp) ? 1.0f : 0.0f;

    const int il = ilen[b];
    const int tl = tlen[b];
    const float* xp = x + (size_t)b * TT * CC;

    float ae = (lane == 1) ? 1.0f : 0.0f;   // beta[2(lane-1)]
    float ao = 0.0f;                        // beta[2(lane-1)+1]
    int   Esum = 0;                         // true beta = stored * 2^Esum
    float bs = 0.0f, bsc = 0.0f;            // Kahan sum of (x0_t - 2)

    auto step = [&](float d) {
        float e  = __expf(d);                        // p_l / p_b
        float op = __shfl_up_sync(FULLMASK, ao, 1);  // lane0: own ao = 0
        float v  = ae + ao;                          // off-chain
        ae = ae + op;
        ao = fmaf(skipf, op, v) * e;
    };
    auto apply = [&](float m) {   // warp-uniform 2^k rescale, center 2^30
        unsigned mb = __float_as_uint(m);
        if (mb >= 0x00800000u && mb < 0x7f800000u) {
            int e = (int)(mb >> 23) - 127;
            int k = 30 - e;
            k = (k > 127) ? 127 : (k < -126 ? -126 : k);
            float sc = __uint_as_float((unsigned)(127 + k) << 23);
            ae *= sc; ao *= sc;
            Esum -= k;
        }
    };
    auto kadd = [&](float y0) {   // Kahan add into (bs, bsc)
        float y = y0 - bsc;
        float t = bs + y;
        bsc = (t - bs) - y;
        bs = t;
    };

    if (il == TT) {
        float cd[8]; float cbs;
        {
            float g = 0.0f;
#pragma unroll
            for (int i = 0; i < 8; ++i) {
                float b0 = xp[i * CC];
                float tv = xp[i * CC + tg];
                cd[i] = valid ? (tv - b0) : -1e30f;   // -1e30 kills ghost lanes
                g += b0;
            }
            cbs = g - 16.0f;
        }
        for (int g = 0; g < TT / 8; ++g) {
            float nd[8]; float nbs = 0.0f;
            if (g + 1 < TT / 8) {
                const float* np = xp + (size_t)(g + 1) * 8 * CC;
                float gsum = 0.0f;
#pragma unroll
                for (int i = 0; i < 8; ++i) {
                    float b0 = np[i * CC];
                    float tv = np[i * CC + tg];
                    nd[i] = valid ? (tv - b0) : -1e30f;
                    gsum += b0;
                }
                nbs = gsum - 16.0f;
            } else {
#pragma unroll
                for (int i = 0; i < 8; ++i) nd[i] = -1e30f;
            }
            kadd(cbs);
            step(cd[0]);
            step(cd[1]);
            step(cd[2]);
            step(cd[3]);
            // deferred max: measured here, butterfly overlaps steps 4..7
            float m = fmaxf(ae, ao);
            step(cd[4]);
            m = fmaxf(m, __shfl_xor_sync(FULLMASK, m, 16));
            step(cd[5]);
            m = fmaxf(m, __shfl_xor_sync(FULLMASK, m, 8));
            step(cd[6]);
            m = fmaxf(m, __shfl_xor_sync(FULLMASK, m, 4));
            step(cd[7]);
            m = fmaxf(m, __shfl_xor_sync(FULLMASK, m, 2));
            m = fmaxf(m, __shfl_xor_sync(FULLMASK, m, 1));
            apply(m);
#pragma unroll
            for (int i = 0; i < 8; ++i) cd[i] = nd[i];
            cbs = nbs;
        }
    } else {
        for (int t = 0; t < il; ++t) {
            const float* r = xp + (size_t)t * CC;
            float b0 = r[0];
            float d = valid ? (r[tg] - b0) : -1e30f;
            kadd(b0 - 2.0f);
            step(d);
            if ((t & 7) == 7) {
                float m = fmaxf(ae, ao);
#pragma unroll
                for (int o = 16; o > 0; o >>= 1)
                    m = fmaxf(m, __shfl_xor_sync(FULLMASK, m, o));
                apply(m);
            }
        }
    }

    // state 2*tl (even) -> lane tl+1 ; state 2*tl-1 (odd) -> lane tl
    float aev = __shfl_sync(FULLMASK, ae, tl + 1);
    float aov = __shfl_sync(FULLMASK, ao, tl);
    double ssum = (double)aev + (double)aov;

    if (ssum >= 8.673617379884035e-19 /* 2^-60 */ && ssum < 6.0e38) {
        if (lane == 0)
            g_ctcraw[b] = log(ssum) + (double)Esum * LN2 + (double)bs;
    } else {
        double raw = ctc_fp64(xp, target, b, il, tl);
        if (lane == 0) g_ctcraw[b] = raw;
    }
}

// ---------------------------------------------------------------------------
// Softmax-denominator pass, width-16, DEPTH-2 software pipeline (validated in
// R14): warp w -> sample b=w/2, 100 rows. Half-warps process two consecutive
// rows per iteration; loads for iteration i+2 issued while processing
// iteration i (6 outstanding loads/warp). Running product P with exponent
// stripping.
// ---------------------------------------------------------------------------
__device__ __forceinline__ void d_body(
    const float* __restrict__ x, const int* __restrict__ ilen, int w)
{
    const int lane = threadIdx.x & 31;
    const int sub  = lane & 15;
    const int half = lane >> 4;
    const int b  = w >> 1;
    const int t0 = (w & 1) * 100;
    const int il = ilen[b];
    const int tend = (il < t0 + 100) ? il : (t0 + 100);

    const float* xp = x + (size_t)b * TT * CC;
    float P = 1.0f;
    int   Le = 0;
    int   it = 0;

    float2 cv[2]; float ct[2];
#pragma unroll
    for (int k = 0; k < 2; ++k) {
        int tk = t0 + 2 * k;
        cv[k] = make_float2(-1e30f, -1e30f); ct[k] = -1e30f;
        if (tk + 2 <= tend) {
            const float* rb = xp + (size_t)(tk + half) * CC;
            cv[k] = ((const float2*)rb)[sub];
            ct[k] = (sub >= 10) ? rb[22 + sub] : -1e30f;
        }
    }
    int t = t0;
    for (; t + 2 <= tend; t += 2, ++it) {
        const int tp = t + 4;
        float2 nv = make_float2(-1e30f, -1e30f);
        float  nt = -1e30f;
        if (tp + 2 <= tend) {
            const float* rb = xp + (size_t)(tp + half) * CC;
            nv = ((const float2*)rb)[sub];
            nt = (sub >= 10) ? rb[22 + sub] : -1e30f;
        }
        float e = __expf(cv[0].x - 2.0f) + __expf(cv[0].y - 2.0f) + __expf(ct[0] - 2.0f);
#pragma unroll
        for (int o = 8; o > 0; o >>= 1)                      // within-half butterfly
            e += __shfl_xor_sync(FULLMASK, e, o);
        P *= e;                                              // own half's row sum
        if ((it & 7) == 7) {                                 // strip exponent
            unsigned pb = __float_as_uint(P);
            Le += (int)(pb >> 23) - 127;
            P = __uint_as_float((pb & 0x807fffffu) | 0x3f800000u);
        }
        cv[0] = cv[1]; ct[0] = ct[1];
        cv[1] = nv;    ct[1] = nt;
    }
    if (t < tend) {                                          // odd remainder: half 0 only
        if (half == 0) {
            const float* rb = xp + (size_t)t * CC;
            float2 v = ((const float2*)rb)[sub];
            float tail = (sub >= 10) ? rb[22 + sub] : -1e30f;
            float e = __expf(v.x - 2.0f) + __expf(v.y - 2.0f) + __expf(tail - 2.0f);
#pragma unroll
            for (int o = 8; o > 0; o >>= 1)
                e += __shfl_xor_sync(0x0000ffffu, e, o);
            P *= e;
        }
    }
    double l2 = (double)Le + log2((double)P);
    double other = __shfl_xor_sync(FULLMASK, l2, 16);
    if (lane == 0) g_d2[w] = l2 + other;                     // sum of both halves
}

// ---------------------------------------------------------------------------
// KL smoothing, 4 rows per warp with BATCHED loads (validated in R14): all 4
// rows' x / ms data requested up front (one latency exposure instead of
// four), then four independent reductions with interleaved butterflies.
// ---------------------------------------------------------------------------
__device__ __forceinline__ float kl4(
    const float* __restrict__ x, const int* __restrict__ target,
    const int* __restrict__ tlen, const int* __restrict__ pos,
    const float* __restrict__ ms, int base)
{
    const int lane = threadIdx.x & 31;
    float2 xv[4];
    float  se[4], so[4], Lr[4];
    bool   act[4];

#pragma unroll
    for (int r = 0; r < 4; ++r) {
        const int idx = base + r;
        const int b = idx / SS;
        const int s = idx - b * SS;
        const int tl = tlen[b];
        act[r] = (s < tl);
        Lr[r]  = (float)tl;
        xv[r]  = make_float2(0.0f, 0.0f);
        se[r]  = 0.0f; so[r] = 0.0f;
        if (act[r]) {
            const int p  = pos[idx];
            const int tg = target[idx];
            const int f  = (s == 0) ? (CC - 1) : target[idx - 1];
            const float* row = x + ((size_t)b * TT + p) * CC;
            const float* msr = ms + ((size_t)(f - 1) * 37 + (tg - 1)) * 37;
            if (lane < 19) {
                xv[r] = ((const float2*)row)[lane];
                se[r] = (lane == 0) ? 0.0f : msr[2 * lane - 1];  // SLS class 2l
                so[r] = msr[2 * lane];                           // SLS class 2l+1
            }
        }
    }

    float Ev[4], Tm[4], Sv[4];
#pragma unroll
    for (int r = 0; r < 4; ++r) {
        if (lane < 19 && act[r]) {
            float te = se[r] + 1e-10f;
            float to = so[r] + 1e-10f;
            Ev[r] = __expf(xv[r].x) + __expf(xv[r].y);
            Tm[r] = te * (__logf(te) - xv[r].x) + to * (__logf(to) - xv[r].y);
            Sv[r] = se[r] + so[r];
        } else {
            Ev[r] = 0.0f; Tm[r] = 0.0f; Sv[r] = 0.0f;
        }
    }
#pragma unroll
    for (int o = 16; o > 0; o >>= 1) {
#pragma unroll
        for (int r = 0; r < 4; ++r) {
            Ev[r] += __shfl_xor_sync(FULLMASK, Ev[r], o);
            Tm[r] += __shfl_xor_sync(FULLMASK, Tm[r], o);
            Sv[r] += __shfl_xor_sync(FULLMASK, Sv[r], o);
        }
    }
    float v = 0.0f;
#pragma unroll
    for (int r = 0; r < 4; ++r) {
        if (act[r]) {
            float lse = __logf(Ev[r]);
            float W = Sv[r] + 38e-10f;                       // sum of t_c
            float klrow = (Tm[r] + lse * W) * (1.0f / (float)CC);
            float smooth = -expm1f(-0.05129329438755058f / Lr[r]);
            v += (smooth / Lr[r]) * Sv[r] * klrow;
        }
    }
    return v;
}

// ---------------------------------------------------------------------------
// Mega-fused kernel: CTC blocks (longest, LPT order) + D blocks + KL blocks.
// NO fence/atomic epilogue (R15 measured it at ~+30us chip-wide).
// ---------------------------------------------------------------------------
__global__ void __launch_bounds__(256) mega_kernel(
    const float* __restrict__ x, const int* __restrict__ target,
    const int* __restrict__ ilen, const int* __restrict__ tlen,
    const int* __restrict__ pos, const float* __restrict__ ms)
{
    const int warp = threadIdx.x >> 5;
    if (blockIdx.x < CTC_BLOCKS) {
        ctc_body(x, target, ilen, tlen, blockIdx.x * 8 + warp);
    } else if (blockIdx.x < CTC_BLOCKS + D_BLOCKS) {
        d_body(x, ilen, (blockIdx.x - CTC_BLOCKS) * 8 + warp);
    } else {
        const int kb = blockIdx.x - CTC_BLOCKS - D_BLOCKS;
        float v = kl4(x, target, tlen, pos, ms, (kb * 8 + warp) * 4);
        __shared__ float ksum[8];
        if ((threadIdx.x & 31) == 0) ksum[warp] = v;
        __syncthreads();
        if (threadIdx.x == 0) {
            float t = 0.0f;
#pragma unroll
            for (int i = 0; i < 8; ++i) t += ksum[i];
            g_klb[kb] = t;
        }
    }
}

// ---------------------------------------------------------------------------
// Single-block deterministic final reduction + per-sample nll finalize.
// (R13-proven; 9.2us measured, mostly launch overhead.)
// ---------------------------------------------------------------------------
__global__ void __launch_bounds__(1024) finalize_kernel(
    const int* __restrict__ tlen, float* __restrict__ out)
{
    __shared__ double sm[1024];
    const int tid = threadIdx.x;
    double acc = 0.0;
#pragma unroll 4
    for (int i = tid; i < KL_BLOCKS; i += 1024)
        acc += (double)g_klb[i];
#pragma unroll 4
    for (int b = tid; b < BB; b += 1024) {
        double lnD = (g_d2[2 * b] + g_d2[2 * b + 1]) * LN2;
        double nll = -(g_ctcraw[b] - lnD);
        if (nll > 1e8) nll = 0.0;                            // zero_infinity
        acc += (nll / (double)tlen[b]) * (1.0 / (double)BB);
    }
    sm[tid] = acc;
    __syncthreads();
    for (int st = 512; st > 0; st >>= 1) {
        if (tid < st) sm[tid] += sm[tid + st];
        __syncthreads();
    }
    if (tid == 0) out[0] = (float)sm[0];
}

// ---------------------------------------------------------------------------
extern "C" void kernel_launch(void* const* d_in, const int* in_sizes, int n_in,
                              void* d_out, int out_size)
{
    const float* x      = (const float*)d_in[0];   // [B,T,C] f32
    const int*   target = (const int*)d_in[1];     // [B,S]   i32
    const int*   ilen   = (const int*)d_in[2];     // [B]     i32
    const int*   tlen   = (const int*)d_in[3];     // [B]     i32
    const int*   pos    = (const int*)d_in[4];     // [B,S]   i32
    const float* ms     = (const float*)d_in[5];   // [37,37,37] f32

    mega_kernel<<<TOTAL_BLOCKS, 256>>>(x, target, ilen, tlen, pos, ms);
    finalize_kernel<<<1, 1024>>>(tlen, (float*)d_out);
}